// round 7
// baseline (speedup 1.0000x reference)
#include <cuda_runtime.h>
#include <cuda_bf16.h>
#include <math.h>

#define B_ 64
#define W_ 4096
#define H_ 128
#define I_ 128
#define CHUNKS 8
#define TPB (W_ / CHUNKS)
#define WARPS 8
#define ROWS_PER_WARP (TPB / WARPS)

__device__ float g_pm[B_ * CHUNKS];
__device__ float g_pl[B_ * CHUNKS];
__device__ float g_pacc[B_ * CHUNKS * H_];

__device__ __forceinline__ float warp_sum(float v) {
    #pragma unroll
    for (int o = 16; o; o >>= 1) v += __shfl_xor_sync(0xffffffffu, v, o);
    return v;
}

__device__ __forceinline__ float sigm(float x) { return 1.0f / (1.0f + expf(-x)); }

__device__ __forceinline__ float dot4(float4 w, float4 v, float acc) {
    acc = fmaf(w.x, v.x, acc);
    acc = fmaf(w.y, v.y, acc);
    acc = fmaf(w.z, v.z, acc);
    acc = fmaf(w.w, v.w, acc);
    return acc;
}

// ---------------------------------------------------------------------------
// Phase 1: fused score + online-softmax weighted accumulate (1 encoder pass).
// (Round-5 known-good version, unchanged.)
// ---------------------------------------------------------------------------
__global__ __launch_bounds__(256, 4)
void attn_partial_kernel(const float* __restrict__ enc,
                         const float* __restrict__ h0,
                         const float* __restrict__ c0,
                         const float* __restrict__ attW,
                         const float* __restrict__ attB)
{
    const int c    = blockIdx.x;
    const int b    = blockIdx.y;
    const int tid  = threadIdx.x;
    const int warp = tid >> 5;
    const int lane = tid & 31;

    __shared__ float s_red[WARPS];
    __shared__ float s_bias;
    __shared__ float s_m[WARPS], s_l[WARPS];
    __shared__ float s_acc[WARPS][H_];

    float part = 0.f;
    if (tid < H_) {
        float hs = h0[(1 * B_ + b) * H_ + tid];
        float cs = c0[(1 * B_ + b) * H_ + tid];
        part = hs * cs * attW[H_ + tid];
    }
    part = warp_sum(part);
    if (lane == 0) s_red[warp] = part;
    __syncthreads();
    if (tid == 0) {
        float s = 0.f;
        #pragma unroll
        for (int w = 0; w < WARPS; w++) s += s_red[w];
        s_bias = s + attB[0];
    }
    __syncthreads();
    const float bias = s_bias;

    const float4 wa = *reinterpret_cast<const float4*>(attW + lane * 4);

    const int rowStart = c * TPB + warp * ROWS_PER_WARP;
    const float* encb = enc + (size_t)b * W_ * H_;

    float prevLogit;
    if (rowStart == 0) {
        prevLogit = 0.0f;
    } else {
        float4 v = *reinterpret_cast<const float4*>(
            encb + (size_t)(rowStart - 1) * H_ + lane * 4);
        float d = v.x * wa.x + v.y * wa.y + v.z * wa.z + v.w * wa.w;
        d = warp_sum(d);
        prevLogit = d + bias;
    }

    float m = -1e30f, l = 0.f;
    float ax = 0.f, ay = 0.f, az = 0.f, aw = 0.f;

    const float* rp = encb + (size_t)rowStart * H_ + lane * 4;
    #pragma unroll 4
    for (int r = 0; r < ROWS_PER_WARP; r++) {
        const float4 v = *reinterpret_cast<const float4*>(rp);
        rp += H_;
        float d = v.x * wa.x + v.y * wa.y + v.z * wa.z + v.w * wa.w;
        d = warp_sum(d);
        const float logit = prevLogit;
        prevLogit = d + bias;
        const float mNew = fmaxf(m, logit);
        const float corr = __expf(m - mNew);
        const float p    = __expf(logit - mNew);
        l  = l * corr + p;
        ax = ax * corr + p * v.x;
        ay = ay * corr + p * v.y;
        az = az * corr + p * v.z;
        aw = aw * corr + p * v.w;
        m = mNew;
    }

    if (lane == 0) { s_m[warp] = m; s_l[warp] = l; }
    s_acc[warp][lane * 4 + 0] = ax;
    s_acc[warp][lane * 4 + 1] = ay;
    s_acc[warp][lane * 4 + 2] = az;
    s_acc[warp][lane * 4 + 3] = aw;
    __syncthreads();

    if (tid < H_) {
        float M = s_m[0];
        #pragma unroll
        for (int w = 1; w < WARPS; w++) M = fmaxf(M, s_m[w]);
        float L = 0.f, A = 0.f;
        #pragma unroll
        for (int w = 0; w < WARPS; w++) {
            const float e = __expf(s_m[w] - M);
            L += s_l[w] * e;
            A += s_acc[w][tid] * e;
        }
        const int pi = b * CHUNKS + c;
        g_pacc[pi * H_ + tid] = A;
        if (tid == 0) { g_pm[pi] = M; g_pl[pi] = L; }
    }
}

// ---------------------------------------------------------------------------
// Fused tail: combine + xin + LSTM0 + LSTM1, all per-batch independent.
// grid = 32 blocks, each handles 2 batch rows (u = tid>>8). 512 threads.
// Activations live in smem (broadcast reads); weights streamed from L2
// (line-coalesced across lanes, shared by both batches).
// out layout: [h2 (B,H)] [h1] [h2] [c1] [c2]
// ---------------------------------------------------------------------------
__global__ __launch_bounds__(512)
void tail_kernel(const float* __restrict__ input,
                 const float* __restrict__ h0,
                 const float* __restrict__ c0,
                 const float* __restrict__ inp_W,
                 const float* __restrict__ inp_b,
                 const float* __restrict__ W_ih0,
                 const float* __restrict__ W_hh0,
                 const float* __restrict__ b_ih0,
                 const float* __restrict__ b_hh0,
                 const float* __restrict__ W_ih1,
                 const float* __restrict__ W_hh1,
                 const float* __restrict__ b_ih1,
                 const float* __restrict__ b_hh1,
                 float* __restrict__ out)
{
    const int bp  = blockIdx.x * 2;
    const int tid = threadIdx.x;

    __shared__ float s_xcat[2][H_ + I_];   // [u][k]  context | input
    __shared__ float s_h0a[2][H_];         // h0 layer 0
    __shared__ float s_h0b[2][H_];         // h0 layer 1
    __shared__ float s_xp[2][2][I_];       // xin partials [u][kh][j]
    __shared__ float s_xin[2][I_];
    __shared__ float s_g[2][4 * H_];
    __shared__ float s_h1[2][H_];

    // ---- Step A: softmax-combine + stage states ----
    {
        const int u = tid >> 8;
        const int k = tid & 255;
        const int b = bp + u;
        if (k < H_) {
            float M = g_pm[b * CHUNKS + 0];
            #pragma unroll
            for (int cc = 1; cc < CHUNKS; cc++) M = fmaxf(M, g_pm[b * CHUNKS + cc]);
            float L = 0.f, A = 0.f;
            #pragma unroll
            for (int cc = 0; cc < CHUNKS; cc++) {
                const float e = __expf(g_pm[b * CHUNKS + cc] - M);
                L += g_pl[b * CHUNKS + cc] * e;
                A += g_pacc[(b * CHUNKS + cc) * H_ + k] * e;
            }
            s_xcat[u][k] = A / L;
            s_h0a[u][k] = h0[(0 * B_ + b) * H_ + k];
            s_h0b[u][k] = h0[(1 * B_ + b) * H_ + k];
        } else {
            s_xcat[u][k] = input[b * I_ + (k - H_)];
        }
    }
    __syncthreads();

    // ---- Step B: xin[j] = xcat . inp_W[j,:] + inp_b[j]  (K=256, split 2) ----
    {
        const int j  = tid & 127;
        const int kh = (tid >> 7) & 1;
        const int u  = tid >> 8;
        const float4* wp = reinterpret_cast<const float4*>(inp_W + j * (H_ + I_) + kh * 128);
        const float4* xp = reinterpret_cast<const float4*>(&s_xcat[u][kh * 128]);
        float acc = (kh == 0) ? inp_b[j] : 0.f;
        #pragma unroll
        for (int t = 0; t < 32; t++) acc = dot4(wp[t], xp[t], acc);
        s_xp[u][kh][j] = acc;
    }
    __syncthreads();
    if (tid < 256) {
        const int u = tid >> 7;
        const int j = tid & 127;
        s_xin[u][j] = s_xp[u][0][j] + s_xp[u][1][j];
    }
    __syncthreads();

    // ---- Step C: LSTM layer 0. thread = gate-row j (512), both batches ----
    {
        const int j = tid;
        const float4* wi = reinterpret_cast<const float4*>(W_ih0 + j * I_);
        const float4* wh = reinterpret_cast<const float4*>(W_hh0 + j * H_);
        const float4* x0 = reinterpret_cast<const float4*>(s_xin[0]);
        const float4* x1 = reinterpret_cast<const float4*>(s_xin[1]);
        const float4* p0 = reinterpret_cast<const float4*>(s_h0a[0]);
        const float4* p1 = reinterpret_cast<const float4*>(s_h0a[1]);
        const float bias = b_ih0[j] + b_hh0[j];
        float a0 = bias, a1 = bias;
        #pragma unroll
        for (int t = 0; t < 32; t++) {
            const float4 w = wi[t];
            a0 = dot4(w, x0[t], a0);
            a1 = dot4(w, x1[t], a1);
        }
        #pragma unroll
        for (int t = 0; t < 32; t++) {
            const float4 w = wh[t];
            a0 = dot4(w, p0[t], a0);
            a1 = dot4(w, p1[t], a1);
        }
        s_g[0][j] = a0;
        s_g[1][j] = a1;
    }
    __syncthreads();
    if (tid < 256) {
        const int u = tid >> 7;
        const int h = tid & 127;
        const int b = bp + u;
        const float gi = s_g[u][h];
        const float gf = s_g[u][H_ + h];
        const float gg = s_g[u][2 * H_ + h];
        const float go = s_g[u][3 * H_ + h];
        const float cp = c0[(0 * B_ + b) * H_ + h];
        const float c1 = sigm(gf) * cp + sigm(gi) * tanhf(gg);
        const float h1 = sigm(go) * tanhf(c1);
        s_h1[u][h] = h1;
        out[1 * B_ * H_ + b * H_ + h] = h1;
        out[3 * B_ * H_ + b * H_ + h] = c1;
    }
    __syncthreads();

    // ---- Step D: LSTM layer 1 ----
    {
        const int j = tid;
        const float4* wi = reinterpret_cast<const float4*>(W_ih1 + j * H_);
        const float4* wh = reinterpret_cast<const float4*>(W_hh1 + j * H_);
        const float4* x0 = reinterpret_cast<const float4*>(s_h1[0]);
        const float4* x1 = reinterpret_cast<const float4*>(s_h1[1]);
        const float4* p0 = reinterpret_cast<const float4*>(s_h0b[0]);
        const float4* p1 = reinterpret_cast<const float4*>(s_h0b[1]);
        const float bias = b_ih1[j] + b_hh1[j];
        float a0 = bias, a1 = bias;
        #pragma unroll
        for (int t = 0; t < 32; t++) {
            const float4 w = wi[t];
            a0 = dot4(w, x0[t], a0);
            a1 = dot4(w, x1[t], a1);
        }
        #pragma unroll
        for (int t = 0; t < 32; t++) {
            const float4 w = wh[t];
            a0 = dot4(w, p0[t], a0);
            a1 = dot4(w, p1[t], a1);
        }
        s_g[0][j] = a0;
        s_g[1][j] = a1;
    }
    __syncthreads();
    if (tid < 256) {
        const int u = tid >> 7;
        const int h = tid & 127;
        const int b = bp + u;
        const float gi = s_g[u][h];
        const float gf = s_g[u][H_ + h];
        const float gg = s_g[u][2 * H_ + h];
        const float go = s_g[u][3 * H_ + h];
        const float cp = c0[(1 * B_ + b) * H_ + h];
        const float c2 = sigm(gf) * cp + sigm(gi) * tanhf(gg);
        const float h2 = sigm(go) * tanhf(c2);
        out[0 * B_ * H_ + b * H_ + h] = h2;
        out[2 * B_ * H_ + b * H_ + h] = h2;
        out[4 * B_ * H_ + b * H_ + h] = c2;
    }
}

extern "C" void kernel_launch(void* const* d_in, const int* in_sizes, int n_in,
                              void* d_out, int out_size) {
    const float* input  = (const float*)d_in[0];
    const float* h0     = (const float*)d_in[1];
    const float* c0     = (const float*)d_in[2];
    const float* enc    = (const float*)d_in[3];
    const float* attW   = (const float*)d_in[4];
    const float* attB   = (const float*)d_in[5];
    const float* inp_W  = (const float*)d_in[6];
    const float* inp_b  = (const float*)d_in[7];
    const float* W_ih0  = (const float*)d_in[8];
    const float* W_hh0  = (const float*)d_in[9];
    const float* b_ih0  = (const float*)d_in[10];
    const float* b_hh0  = (const float*)d_in[11];
    const float* W_ih1  = (const float*)d_in[12];
    const float* W_hh1  = (const float*)d_in[13];
    const float* b_ih1  = (const float*)d_in[14];
    const float* b_hh1  = (const float*)d_in[15];
    float* out = (float*)d_out;

    dim3 grid1(CHUNKS, B_);
    attn_partial_kernel<<<grid1, 256>>>(enc, h0, c0, attW, attB);
    tail_kernel<<<B_ / 2, 512>>>(input, h0, c0, inp_W, inp_b,
                                 W_ih0, W_hh0, b_ih0, b_hh0,
                                 W_ih1, W_hh1, b_ih1, b_hh1, out);
}

// round 8
// speedup vs baseline: 1.7640x; 1.7640x over previous
#include <cuda_runtime.h>
#include <cuda_bf16.h>
#include <math.h>

#define B_ 64
#define W_ 4096
#define H_ 128
#define I_ 128
#define CHUNKS 8
#define TPB (W_ / CHUNKS)
#define WARPS 8
#define ROWS_PER_WARP (TPB / WARPS)

__device__ float g_pm[B_ * CHUNKS];
__device__ float g_pl[B_ * CHUNKS];
__device__ float g_pacc[B_ * CHUNKS * H_];

// Transposed activations [k][b]
__device__ float g_xcatT[(H_ + I_) * B_];
__device__ float g_xinT[I_ * B_];
__device__ float g_h1T[H_ * B_];
__device__ float g_h0T0[H_ * B_];
__device__ float g_h0T1[H_ * B_];

__device__ __forceinline__ float warp_sum(float v) {
    #pragma unroll
    for (int o = 16; o; o >>= 1) v += __shfl_xor_sync(0xffffffffu, v, o);
    return v;
}

__device__ __forceinline__ float sigm(float x) { return 1.0f / (1.0f + expf(-x)); }

// ---------------------------------------------------------------------------
// Phase 1: fused score + online-softmax weighted accumulate (1 encoder pass).
// ---------------------------------------------------------------------------
__global__ __launch_bounds__(256, 4)
void attn_partial_kernel(const float* __restrict__ enc,
                         const float* __restrict__ h0,
                         const float* __restrict__ c0,
                         const float* __restrict__ attW,
                         const float* __restrict__ attB)
{
    const int c    = blockIdx.x;
    const int b    = blockIdx.y;
    const int tid  = threadIdx.x;
    const int warp = tid >> 5;
    const int lane = tid & 31;

    __shared__ float s_red[WARPS];
    __shared__ float s_bias;
    __shared__ float s_m[WARPS], s_l[WARPS];
    __shared__ float s_acc[WARPS][H_];

    float part = 0.f;
    if (tid < H_) {
        float hs = h0[(1 * B_ + b) * H_ + tid];
        float cs = c0[(1 * B_ + b) * H_ + tid];
        part = hs * cs * attW[H_ + tid];
    }
    part = warp_sum(part);
    if (lane == 0) s_red[warp] = part;
    __syncthreads();
    if (tid == 0) {
        float s = 0.f;
        #pragma unroll
        for (int w = 0; w < WARPS; w++) s += s_red[w];
        s_bias = s + attB[0];
    }
    __syncthreads();
    const float bias = s_bias;

    const float4 wa = *reinterpret_cast<const float4*>(attW + lane * 4);

    const int rowStart = c * TPB + warp * ROWS_PER_WARP;
    const float* encb = enc + (size_t)b * W_ * H_;

    float prevLogit;
    if (rowStart == 0) {
        prevLogit = 0.0f;
    } else {
        float4 v = *reinterpret_cast<const float4*>(
            encb + (size_t)(rowStart - 1) * H_ + lane * 4);
        float d = v.x * wa.x + v.y * wa.y + v.z * wa.z + v.w * wa.w;
        d = warp_sum(d);
        prevLogit = d + bias;
    }

    float m = -1e30f, l = 0.f;
    float ax = 0.f, ay = 0.f, az = 0.f, aw = 0.f;

    const float* rp = encb + (size_t)rowStart * H_ + lane * 4;
    #pragma unroll 4
    for (int r = 0; r < ROWS_PER_WARP; r++) {
        const float4 v = *reinterpret_cast<const float4*>(rp);
        rp += H_;
        float d = v.x * wa.x + v.y * wa.y + v.z * wa.z + v.w * wa.w;
        d = warp_sum(d);
        const float logit = prevLogit;
        prevLogit = d + bias;
        const float mNew = fmaxf(m, logit);
        const float corr = __expf(m - mNew);
        const float p    = __expf(logit - mNew);
        l  = l * corr + p;
        ax = ax * corr + p * v.x;
        ay = ay * corr + p * v.y;
        az = az * corr + p * v.z;
        aw = aw * corr + p * v.w;
        m = mNew;
    }

    if (lane == 0) { s_m[warp] = m; s_l[warp] = l; }
    s_acc[warp][lane * 4 + 0] = ax;
    s_acc[warp][lane * 4 + 1] = ay;
    s_acc[warp][lane * 4 + 2] = az;
    s_acc[warp][lane * 4 + 3] = aw;
    __syncthreads();

    if (tid < H_) {
        float M = s_m[0];
        #pragma unroll
        for (int w = 1; w < WARPS; w++) M = fmaxf(M, s_m[w]);
        float L = 0.f, A = 0.f;
        #pragma unroll
        for (int w = 0; w < WARPS; w++) {
            const float e = __expf(s_m[w] - M);
            L += s_l[w] * e;
            A += s_acc[w][tid] * e;
        }
        const int pi = b * CHUNKS + c;
        g_pacc[pi * H_ + tid] = A;
        if (tid == 0) { g_pm[pi] = M; g_pl[pi] = L; }
    }
}

// ---------------------------------------------------------------------------
// K2: combine chunk partials -> xcatT; transpose h0 states.
// ---------------------------------------------------------------------------
__global__ __launch_bounds__(256, 1)
void combine_kernel(const float* __restrict__ input,
                    const float* __restrict__ h0)
{
    const int b = blockIdx.x;
    const int k = threadIdx.x;

    if (k < H_) {
        float M = g_pm[b * CHUNKS + 0];
        #pragma unroll
        for (int cc = 1; cc < CHUNKS; cc++) M = fmaxf(M, g_pm[b * CHUNKS + cc]);
        float L = 0.f, A = 0.f;
        #pragma unroll
        for (int cc = 0; cc < CHUNKS; cc++) {
            const float e = __expf(g_pm[b * CHUNKS + cc] - M);
            L += g_pl[b * CHUNKS + cc] * e;
            A += g_pacc[(b * CHUNKS + cc) * H_ + k] * e;
        }
        g_xcatT[k * B_ + b] = A / L;
        g_h0T0[k * B_ + b] = h0[(0 * B_ + b) * H_ + k];
        g_h0T1[k * B_ + b] = h0[(1 * B_ + b) * H_ + k];
    } else {
        g_xcatT[k * B_ + b] = input[b * I_ + (k - H_)];
    }
}

// ---------------------------------------------------------------------------
// K3: xin GEMV, K split in half across threads.
// grid = 64 blocks (2 j each), 256 threads: bits [5:0]=b, [6]=jl, [7]=khalf.
// ---------------------------------------------------------------------------
__global__ __launch_bounds__(256, 1)
void xin_kernel(const float* __restrict__ inp_W,
                const float* __restrict__ inp_b)
{
    const int tid   = threadIdx.x;
    const int b     = tid & 63;
    const int jl    = (tid >> 6) & 1;
    const int khalf = tid >> 7;
    const int j     = blockIdx.x * 2 + jl;

    __shared__ float s_w[2][H_ + I_];
    __shared__ float s_part[2][2][B_];

    const float* wbase = inp_W + blockIdx.x * 2 * (H_ + I_);
    #pragma unroll
    for (int i = tid; i < 2 * (H_ + I_); i += 256) {
        s_w[i >> 8][i & 255] = wbase[i];
    }
    __syncthreads();

    const float* wp = &s_w[jl][khalf * 128];
    const float* ap = &g_xcatT[khalf * 128 * B_];
    float acc = (khalf == 0) ? inp_b[j] : 0.f;
    #pragma unroll
    for (int kk = 0; kk < 128; kk += 8) {
        float v0 = ap[(kk + 0) * B_ + b];
        float v1 = ap[(kk + 1) * B_ + b];
        float v2 = ap[(kk + 2) * B_ + b];
        float v3 = ap[(kk + 3) * B_ + b];
        float v4 = ap[(kk + 4) * B_ + b];
        float v5 = ap[(kk + 5) * B_ + b];
        float v6 = ap[(kk + 6) * B_ + b];
        float v7 = ap[(kk + 7) * B_ + b];
        acc = fmaf(wp[kk + 0], v0, acc);
        acc = fmaf(wp[kk + 1], v1, acc);
        acc = fmaf(wp[kk + 2], v2, acc);
        acc = fmaf(wp[kk + 3], v3, acc);
        acc = fmaf(wp[kk + 4], v4, acc);
        acc = fmaf(wp[kk + 5], v5, acc);
        acc = fmaf(wp[kk + 6], v6, acc);
        acc = fmaf(wp[kk + 7], v7, acc);
    }
    s_part[khalf][jl][b] = acc;
    __syncthreads();

    if (tid < 128) {
        const int jl2 = tid >> 6;
        const int bb  = tid & 63;
        g_xinT[(blockIdx.x * 2 + jl2) * B_ + bb] =
            s_part[0][jl2][bb] + s_part[1][jl2][bb];
    }
}

// ---------------------------------------------------------------------------
// K4/K5: LSTM cell. grid = H_ blocks (h), 512 threads:
// bits [5:0]=b, [7:6]=gate, [8]=khalf (0: x-part, 1: h-part).
// Each thread: 128-MAC chain with 8-deep explicit load batches.
// __launch_bounds__(512, 1): single-wave grid, let ptxas use ~96 regs so the
// 8-load batches stay in flight (MLP ~8) instead of being serialized at 32 regs.
// ---------------------------------------------------------------------------
__global__ __launch_bounds__(512, 1)
void lstm_cell_kernel(const float* __restrict__ xT,
                      const float* __restrict__ hT,
                      const float* __restrict__ W_ih,
                      const float* __restrict__ W_hh,
                      const float* __restrict__ b_ih,
                      const float* __restrict__ b_hh,
                      const float* __restrict__ cPrev,
                      float* __restrict__ outH,
                      float* __restrict__ outH2,
                      float* __restrict__ outC,
                      float* __restrict__ hT_out)
{
    const int h     = blockIdx.x;
    const int tid   = threadIdx.x;
    const int b     = tid & 63;
    const int gate  = (tid >> 6) & 3;
    const int khalf = tid >> 8;
    const int j     = gate * H_ + h;

    __shared__ float s_w[4][2 * H_];     // [gate][ W_ih row | W_hh row ]
    __shared__ float s_part[2][4][B_];

    #pragma unroll
    for (int i = tid; i < 4 * 2 * H_; i += 512) {
        const int g = i >> 8;
        const int k = i & 255;
        s_w[g][k] = (k < H_) ? W_ih[(g * H_ + h) * H_ + k]
                             : W_hh[(g * H_ + h) * H_ + (k - H_)];
    }
    __syncthreads();

    const float* wp = &s_w[gate][khalf * H_];
    const float* ap = (khalf == 0) ? xT : hT;
    float acc = (khalf == 0) ? b_ih[j] : b_hh[j];
    #pragma unroll
    for (int kk = 0; kk < H_; kk += 8) {
        float v0 = ap[(kk + 0) * B_ + b];
        float v1 = ap[(kk + 1) * B_ + b];
        float v2 = ap[(kk + 2) * B_ + b];
        float v3 = ap[(kk + 3) * B_ + b];
        float v4 = ap[(kk + 4) * B_ + b];
        float v5 = ap[(kk + 5) * B_ + b];
        float v6 = ap[(kk + 6) * B_ + b];
        float v7 = ap[(kk + 7) * B_ + b];
        acc = fmaf(wp[kk + 0], v0, acc);
        acc = fmaf(wp[kk + 1], v1, acc);
        acc = fmaf(wp[kk + 2], v2, acc);
        acc = fmaf(wp[kk + 3], v3, acc);
        acc = fmaf(wp[kk + 4], v4, acc);
        acc = fmaf(wp[kk + 5], v5, acc);
        acc = fmaf(wp[kk + 6], v6, acc);
        acc = fmaf(wp[kk + 7], v7, acc);
    }
    s_part[khalf][gate][b] = acc;
    __syncthreads();

    if (tid < B_) {
        const int bb = tid;
        const float gi = s_part[0][0][bb] + s_part[1][0][bb];
        const float gf = s_part[0][1][bb] + s_part[1][1][bb];
        const float gg = s_part[0][2][bb] + s_part[1][2][bb];
        const float go = s_part[0][3][bb] + s_part[1][3][bb];
        const float cp = cPrev[bb * H_ + h];
        const float cN = sigm(gf) * cp + sigm(gi) * tanhf(gg);
        const float hN = sigm(go) * tanhf(cN);
        outH[bb * H_ + h] = hN;
        if (outH2) outH2[bb * H_ + h] = hN;
        outC[bb * H_ + h] = cN;
        if (hT_out) hT_out[h * B_ + bb] = hN;
    }
}

extern "C" void kernel_launch(void* const* d_in, const int* in_sizes, int n_in,
                              void* d_out, int out_size) {
    const float* input  = (const float*)d_in[0];
    const float* h0     = (const float*)d_in[1];
    const float* c0     = (const float*)d_in[2];
    const float* enc    = (const float*)d_in[3];
    const float* attW   = (const float*)d_in[4];
    const float* attB   = (const float*)d_in[5];
    const float* inp_W  = (const float*)d_in[6];
    const float* inp_b  = (const float*)d_in[7];
    const float* W_ih0  = (const float*)d_in[8];
    const float* W_hh0  = (const float*)d_in[9];
    const float* b_ih0  = (const float*)d_in[10];
    const float* b_hh0  = (const float*)d_in[11];
    const float* W_ih1  = (const float*)d_in[12];
    const float* W_hh1  = (const float*)d_in[13];
    const float* b_ih1  = (const float*)d_in[14];
    const float* b_hh1  = (const float*)d_in[15];
    float* out = (float*)d_out;

    float* out_y  = out + 0 * B_ * H_;
    float* out_h1 = out + 1 * B_ * H_;
    float* out_h2 = out + 2 * B_ * H_;
    float* out_c1 = out + 3 * B_ * H_;
    float* out_c2 = out + 4 * B_ * H_;

    float* xinT;  cudaGetSymbolAddress((void**)&xinT,  g_xinT);
    float* h1T;   cudaGetSymbolAddress((void**)&h1T,   g_h1T);
    float* h0T0;  cudaGetSymbolAddress((void**)&h0T0,  g_h0T0);
    float* h0T1;  cudaGetSymbolAddress((void**)&h0T1,  g_h0T1);

    dim3 grid1(CHUNKS, B_);
    attn_partial_kernel<<<grid1, 256>>>(enc, h0, c0, attW, attB);
    combine_kernel<<<B_, 256>>>(input, h0);
    xin_kernel<<<I_ / 2, 256>>>(inp_W, inp_b);
    lstm_cell_kernel<<<H_, 512>>>(xinT, h0T0, W_ih0, W_hh0, b_ih0, b_hh0,
                                  c0 + 0 * B_ * H_,
                                  out_h1, nullptr, out_c1, h1T);
    lstm_cell_kernel<<<H_, 512>>>(h1T, h0T1, W_ih1, W_hh1, b_ih1, b_hh1,
                                  c0 + 1 * B_ * H_,
                                  out_y, out_h2, out_c2, nullptr);
}

// round 9
// speedup vs baseline: 1.8532x; 1.0506x over previous
#include <cuda_runtime.h>
#include <cuda_bf16.h>
#include <math.h>

#define B_ 64
#define W_ 4096
#define H_ 128
#define I_ 128
#define CHUNKS 8
#define TPB (W_ / CHUNKS)
#define WARPS 8
#define ROWS_PER_WARP (TPB / WARPS)

__device__ float g_pm[B_ * CHUNKS];
__device__ float g_pl[B_ * CHUNKS];
__device__ float g_pacc[B_ * CHUNKS * H_];

// Transposed activations [k][b]
__device__ float g_xcatT[(H_ + I_) * B_];
__device__ float g_xinT[I_ * B_];
__device__ float g_h1T[H_ * B_];
__device__ float g_h0T0[H_ * B_];
__device__ float g_h0T1[H_ * B_];

__device__ __forceinline__ float warp_sum(float v) {
    #pragma unroll
    for (int o = 16; o; o >>= 1) v += __shfl_xor_sync(0xffffffffu, v, o);
    return v;
}

__device__ __forceinline__ float sigm(float x) { return 1.0f / (1.0f + expf(-x)); }

// ---------------------------------------------------------------------------
// Phase 1: fused score + online-softmax weighted accumulate (1 encoder pass).
// v2: 2 rows per iteration — interleaved SHFL reduce chains, one combined
// softmax rescale per pair. Halves the serial per-row cost and doubles MLP.
// ---------------------------------------------------------------------------
__global__ __launch_bounds__(256, 4)
void attn_partial_kernel(const float* __restrict__ enc,
                         const float* __restrict__ h0,
                         const float* __restrict__ c0,
                         const float* __restrict__ attW,
                         const float* __restrict__ attB)
{
    const int c    = blockIdx.x;
    const int b    = blockIdx.y;
    const int tid  = threadIdx.x;
    const int warp = tid >> 5;
    const int lane = tid & 31;

    __shared__ float s_red[WARPS];
    __shared__ float s_bias;
    __shared__ float s_m[WARPS], s_l[WARPS];
    __shared__ float s_acc[WARPS][H_];

    float part = 0.f;
    if (tid < H_) {
        float hs = h0[(1 * B_ + b) * H_ + tid];
        float cs = c0[(1 * B_ + b) * H_ + tid];
        part = hs * cs * attW[H_ + tid];
    }
    part = warp_sum(part);
    if (lane == 0) s_red[warp] = part;
    __syncthreads();
    if (tid == 0) {
        float s = 0.f;
        #pragma unroll
        for (int w = 0; w < WARPS; w++) s += s_red[w];
        s_bias = s + attB[0];
    }
    __syncthreads();
    const float bias = s_bias;

    const float4 wa = *reinterpret_cast<const float4*>(attW + lane * 4);

    const int rowStart = c * TPB + warp * ROWS_PER_WARP;
    const float* encb = enc + (size_t)b * W_ * H_;

    float prevLogit;
    if (rowStart == 0) {
        prevLogit = 0.0f;
    } else {
        float4 v = *reinterpret_cast<const float4*>(
            encb + (size_t)(rowStart - 1) * H_ + lane * 4);
        float d = v.x * wa.x + v.y * wa.y + v.z * wa.z + v.w * wa.w;
        d = warp_sum(d);
        prevLogit = d + bias;
    }

    float m = -1e30f, l = 0.f;
    float ax = 0.f, ay = 0.f, az = 0.f, aw = 0.f;

    const float* rp = encb + (size_t)rowStart * H_ + lane * 4;
    #pragma unroll 4
    for (int it = 0; it < ROWS_PER_WARP / 2; it++) {
        const float4 v0 = *reinterpret_cast<const float4*>(rp);
        const float4 v1 = *reinterpret_cast<const float4*>(rp + H_);
        rp += 2 * H_;
        float d0 = v0.x * wa.x + v0.y * wa.y + v0.z * wa.z + v0.w * wa.w;
        float d1 = v1.x * wa.x + v1.y * wa.y + v1.z * wa.z + v1.w * wa.w;
        // two interleaved butterfly reductions (chains pipeline)
        #pragma unroll
        for (int o = 16; o; o >>= 1) {
            d0 += __shfl_xor_sync(0xffffffffu, d0, o);
            d1 += __shfl_xor_sync(0xffffffffu, d1, o);
        }
        const float logit0 = prevLogit;
        const float logit1 = d0 + bias;
        prevLogit = d1 + bias;
        // combined online-softmax update for the pair
        const float mNew = fmaxf(m, fmaxf(logit0, logit1));
        const float corr = __expf(m - mNew);
        const float p0   = __expf(logit0 - mNew);
        const float p1   = __expf(logit1 - mNew);
        l  = l * corr + p0 + p1;
        ax = ax * corr + p0 * v0.x + p1 * v1.x;
        ay = ay * corr + p0 * v0.y + p1 * v1.y;
        az = az * corr + p0 * v0.z + p1 * v1.z;
        aw = aw * corr + p0 * v0.w + p1 * v1.w;
        m = mNew;
    }

    if (lane == 0) { s_m[warp] = m; s_l[warp] = l; }
    s_acc[warp][lane * 4 + 0] = ax;
    s_acc[warp][lane * 4 + 1] = ay;
    s_acc[warp][lane * 4 + 2] = az;
    s_acc[warp][lane * 4 + 3] = aw;
    __syncthreads();

    if (tid < H_) {
        float M = s_m[0];
        #pragma unroll
        for (int w = 1; w < WARPS; w++) M = fmaxf(M, s_m[w]);
        float L = 0.f, A = 0.f;
        #pragma unroll
        for (int w = 0; w < WARPS; w++) {
            const float e = __expf(s_m[w] - M);
            L += s_l[w] * e;
            A += s_acc[w][tid] * e;
        }
        const int pi = b * CHUNKS + c;
        g_pacc[pi * H_ + tid] = A;
        if (tid == 0) { g_pm[pi] = M; g_pl[pi] = L; }
    }
}

// ---------------------------------------------------------------------------
// K2: combine chunk partials -> xcatT; transpose h0 states.
// ---------------------------------------------------------------------------
__global__ __launch_bounds__(256, 1)
void combine_kernel(const float* __restrict__ input,
                    const float* __restrict__ h0)
{
    const int b = blockIdx.x;
    const int k = threadIdx.x;

    if (k < H_) {
        float M = g_pm[b * CHUNKS + 0];
        #pragma unroll
        for (int cc = 1; cc < CHUNKS; cc++) M = fmaxf(M, g_pm[b * CHUNKS + cc]);
        float L = 0.f, A = 0.f;
        #pragma unroll
        for (int cc = 0; cc < CHUNKS; cc++) {
            const float e = __expf(g_pm[b * CHUNKS + cc] - M);
            L += g_pl[b * CHUNKS + cc] * e;
            A += g_pacc[(b * CHUNKS + cc) * H_ + k] * e;
        }
        g_xcatT[k * B_ + b] = A / L;
        g_h0T0[k * B_ + b] = h0[(0 * B_ + b) * H_ + k];
        g_h0T1[k * B_ + b] = h0[(1 * B_ + b) * H_ + k];
    } else {
        g_xcatT[k * B_ + b] = input[b * I_ + (k - H_)];
    }
}

// ---------------------------------------------------------------------------
// K3: xin GEMV, K split in half across threads.
// ---------------------------------------------------------------------------
__global__ __launch_bounds__(256, 1)
void xin_kernel(const float* __restrict__ inp_W,
                const float* __restrict__ inp_b)
{
    const int tid   = threadIdx.x;
    const int b     = tid & 63;
    const int jl    = (tid >> 6) & 1;
    const int khalf = tid >> 7;
    const int j     = blockIdx.x * 2 + jl;

    __shared__ float s_w[2][H_ + I_];
    __shared__ float s_part[2][2][B_];

    const float* wbase = inp_W + blockIdx.x * 2 * (H_ + I_);
    #pragma unroll
    for (int i = tid; i < 2 * (H_ + I_); i += 256) {
        s_w[i >> 8][i & 255] = wbase[i];
    }
    __syncthreads();

    const float* wp = &s_w[jl][khalf * 128];
    const float* ap = &g_xcatT[khalf * 128 * B_];
    float acc = (khalf == 0) ? inp_b[j] : 0.f;
    #pragma unroll
    for (int kk = 0; kk < 128; kk += 8) {
        float v0 = ap[(kk + 0) * B_ + b];
        float v1 = ap[(kk + 1) * B_ + b];
        float v2 = ap[(kk + 2) * B_ + b];
        float v3 = ap[(kk + 3) * B_ + b];
        float v4 = ap[(kk + 4) * B_ + b];
        float v5 = ap[(kk + 5) * B_ + b];
        float v6 = ap[(kk + 6) * B_ + b];
        float v7 = ap[(kk + 7) * B_ + b];
        acc = fmaf(wp[kk + 0], v0, acc);
        acc = fmaf(wp[kk + 1], v1, acc);
        acc = fmaf(wp[kk + 2], v2, acc);
        acc = fmaf(wp[kk + 3], v3, acc);
        acc = fmaf(wp[kk + 4], v4, acc);
        acc = fmaf(wp[kk + 5], v5, acc);
        acc = fmaf(wp[kk + 6], v6, acc);
        acc = fmaf(wp[kk + 7], v7, acc);
    }
    s_part[khalf][jl][b] = acc;
    __syncthreads();

    if (tid < 128) {
        const int jl2 = tid >> 6;
        const int bb  = tid & 63;
        g_xinT[(blockIdx.x * 2 + jl2) * B_ + bb] =
            s_part[0][jl2][bb] + s_part[1][jl2][bb];
    }
}

// ---------------------------------------------------------------------------
// K4/K5: LSTM cell (Round-8 winner, unchanged).
// ---------------------------------------------------------------------------
__global__ __launch_bounds__(512, 1)
void lstm_cell_kernel(const float* __restrict__ xT,
                      const float* __restrict__ hT,
                      const float* __restrict__ W_ih,
                      const float* __restrict__ W_hh,
                      const float* __restrict__ b_ih,
                      const float* __restrict__ b_hh,
                      const float* __restrict__ cPrev,
                      float* __restrict__ outH,
                      float* __restrict__ outH2,
                      float* __restrict__ outC,
                      float* __restrict__ hT_out)
{
    const int h     = blockIdx.x;
    const int tid   = threadIdx.x;
    const int b     = tid & 63;
    const int gate  = (tid >> 6) & 3;
    const int khalf = tid >> 8;
    const int j     = gate * H_ + h;

    __shared__ float s_w[4][2 * H_];
    __shared__ float s_part[2][4][B_];

    #pragma unroll
    for (int i = tid; i < 4 * 2 * H_; i += 512) {
        const int g = i >> 8;
        const int k = i & 255;
        s_w[g][k] = (k < H_) ? W_ih[(g * H_ + h) * H_ + k]
                             : W_hh[(g * H_ + h) * H_ + (k - H_)];
    }
    __syncthreads();

    const float* wp = &s_w[gate][khalf * H_];
    const float* ap = (khalf == 0) ? xT : hT;
    float acc = (khalf == 0) ? b_ih[j] : b_hh[j];
    #pragma unroll
    for (int kk = 0; kk < H_; kk += 8) {
        float v0 = ap[(kk + 0) * B_ + b];
        float v1 = ap[(kk + 1) * B_ + b];
        float v2 = ap[(kk + 2) * B_ + b];
        float v3 = ap[(kk + 3) * B_ + b];
        float v4 = ap[(kk + 4) * B_ + b];
        float v5 = ap[(kk + 5) * B_ + b];
        float v6 = ap[(kk + 6) * B_ + b];
        float v7 = ap[(kk + 7) * B_ + b];
        acc = fmaf(wp[kk + 0], v0, acc);
        acc = fmaf(wp[kk + 1], v1, acc);
        acc = fmaf(wp[kk + 2], v2, acc);
        acc = fmaf(wp[kk + 3], v3, acc);
        acc = fmaf(wp[kk + 4], v4, acc);
        acc = fmaf(wp[kk + 5], v5, acc);
        acc = fmaf(wp[kk + 6], v6, acc);
        acc = fmaf(wp[kk + 7], v7, acc);
    }
    s_part[khalf][gate][b] = acc;
    __syncthreads();

    if (tid < B_) {
        const int bb = tid;
        const float gi = s_part[0][0][bb] + s_part[1][0][bb];
        const float gf = s_part[0][1][bb] + s_part[1][1][bb];
        const float gg = s_part[0][2][bb] + s_part[1][2][bb];
        const float go = s_part[0][3][bb] + s_part[1][3][bb];
        const float cp = cPrev[bb * H_ + h];
        const float cN = sigm(gf) * cp + sigm(gi) * tanhf(gg);
        const float hN = sigm(go) * tanhf(cN);
        outH[bb * H_ + h] = hN;
        if (outH2) outH2[bb * H_ + h] = hN;
        outC[bb * H_ + h] = cN;
        if (hT_out) hT_out[h * B_ + bb] = hN;
    }
}

extern "C" void kernel_launch(void* const* d_in, const int* in_sizes, int n_in,
                              void* d_out, int out_size) {
    const float* input  = (const float*)d_in[0];
    const float* h0     = (const float*)d_in[1];
    const float* c0     = (const float*)d_in[2];
    const float* enc    = (const float*)d_in[3];
    const float* attW   = (const float*)d_in[4];
    const float* attB   = (const float*)d_in[5];
    const float* inp_W  = (const float*)d_in[6];
    const float* inp_b  = (const float*)d_in[7];
    const float* W_ih0  = (const float*)d_in[8];
    const float* W_hh0  = (const float*)d_in[9];
    const float* b_ih0  = (const float*)d_in[10];
    const float* b_hh0  = (const float*)d_in[11];
    const float* W_ih1  = (const float*)d_in[12];
    const float* W_hh1  = (const float*)d_in[13];
    const float* b_ih1  = (const float*)d_in[14];
    const float* b_hh1  = (const float*)d_in[15];
    float* out = (float*)d_out;

    float* out_y  = out + 0 * B_ * H_;
    float* out_h1 = out + 1 * B_ * H_;
    float* out_h2 = out + 2 * B_ * H_;
    float* out_c1 = out + 3 * B_ * H_;
    float* out_c2 = out + 4 * B_ * H_;

    float* xinT;  cudaGetSymbolAddress((void**)&xinT,  g_xinT);
    float* h1T;   cudaGetSymbolAddress((void**)&h1T,   g_h1T);
    float* h0T0;  cudaGetSymbolAddress((void**)&h0T0,  g_h0T0);
    float* h0T1;  cudaGetSymbolAddress((void**)&h0T1,  g_h0T1);

    dim3 grid1(CHUNKS, B_);
    attn_partial_kernel<<<grid1, 256>>>(enc, h0, c0, attW, attB);
    combine_kernel<<<B_, 256>>>(input, h0);
    xin_kernel<<<I_ / 2, 256>>>(inp_W, inp_b);
    lstm_cell_kernel<<<H_, 512>>>(xinT, h0T0, W_ih0, W_hh0, b_ih0, b_hh0,
                                  c0 + 0 * B_ * H_,
                                  out_h1, nullptr, out_c1, h1T);
    lstm_cell_kernel<<<H_, 512>>>(h1T, h0T1, W_ih1, W_hh1, b_ih1, b_hh1,
                                  c0 + 1 * B_ * H_,
                                  out_y, out_h2, out_c2, nullptr);
}